// round 14
// baseline (speedup 1.0000x reference)
#include <cuda_runtime.h>
#include <cuda_fp16.h>
#include <math.h>
#include <stdint.h>

// Problem constants: B=4, T=8192, C=512, W=64 -> S=128, N=256, heads=8, hd=64
#define BSZ   4
#define TTOT  8192
#define CDIM  512
#define WDIL  64
#define NHEAD 8
#define HDIM  64
#define MROWS (BSZ * TTOT)   // 32768
#define BROWS TTOT           // rows per batch = 8192

// ---------------------------------------------------------------------------
// Scratch (static device memory; no allocation allowed)
// ---------------------------------------------------------------------------
__device__ __align__(1024) __half g_xh[(size_t)MROWS * CDIM];      // x fp16
__device__ __align__(1024) float  g_Qf[(size_t)MROWS * CDIM];      // Q fp32
__device__ __align__(1024) __half g_Kh[(size_t)MROWS * CDIM];      // K fp16
__device__ __align__(1024) __half g_Vh[(size_t)MROWS * CDIM];      // V fp16
__device__ __align__(1024) __half g_Oh[(size_t)MROWS * CDIM];      // attn out fp16
__device__ __align__(1024) __half g_Bq[(size_t)3 * CDIM * CDIM];   // QKV W^T [1536,512] K-major
__device__ __align__(1024) __half g_Bo[(size_t)CDIM * CDIM];       // Wo^T [512,512] K-major
__device__ float g_cos[128 * 32];                                  // RoPE tables
__device__ float g_sin[128 * 32];

// ---------------------------------------------------------------------------
// PTX helpers (sm_80-class only: cp.async, ldmatrix, mma.sync)
// ---------------------------------------------------------------------------
__device__ __forceinline__ uint32_t smem_to_u32(const void* p) {
    uint32_t a;
    asm("{ .reg .u64 t; cvta.to.shared.u64 t, %1; cvt.u32.u64 %0, t; }" : "=r"(a) : "l"(p));
    return a;
}
#define CP_ASYNC16(smaddr, gptr) \
    asm volatile("cp.async.cg.shared.global [%0], [%1], 16;" :: "r"(smaddr), "l"(gptr) : "memory")
#define CP_COMMIT() asm volatile("cp.async.commit_group;" ::: "memory")
template <int N> __device__ __forceinline__ void cp_wait() {
    asm volatile("cp.async.wait_group %0;" :: "n"(N) : "memory");
}
__device__ __forceinline__ void ldsm4(uint32_t* r, uint32_t addr) {
    asm volatile("ldmatrix.sync.aligned.m8n8.x4.shared.b16 {%0,%1,%2,%3}, [%4];"
                 : "=r"(r[0]), "=r"(r[1]), "=r"(r[2]), "=r"(r[3]) : "r"(addr));
}
__device__ __forceinline__ void ldsm4t(uint32_t* r, uint32_t addr) {
    asm volatile("ldmatrix.sync.aligned.m8n8.x4.trans.shared.b16 {%0,%1,%2,%3}, [%4];"
                 : "=r"(r[0]), "=r"(r[1]), "=r"(r[2]), "=r"(r[3]) : "r"(addr));
}
__device__ __forceinline__ void mma2(float* d, const uint32_t* a, uint32_t b0, uint32_t b1) {
    asm volatile("mma.sync.aligned.m16n8k16.row.col.f32.f16.f16.f32 "
                 "{%0,%1,%2,%3}, {%4,%5,%6,%7}, {%8,%9}, {%0,%1,%2,%3};"
                 : "+f"(d[0]), "+f"(d[1]), "+f"(d[2]), "+f"(d[3])
                 : "r"(a[0]), "r"(a[1]), "r"(a[2]), "r"(a[3]), "r"(b0), "r"(b1));
}
__device__ __forceinline__ float ex2f(float x) {
    float y; asm("ex2.approx.ftz.f32 %0, %1;" : "=f"(y) : "f"(x)); return y;
}
__device__ __forceinline__ uint32_t packh(float x, float y) {
    __half2 t = __floats2half2_rn(x, y);
    return *(uint32_t*)&t;
}
#define SWZ64(off) ((off) ^ (((off) >> 3) & 0x30))

// ---------------------------------------------------------------------------
// Fused prep kernel: conv_x | conv_wqkv | conv_wo | rope tables, one launch.
// ---------------------------------------------------------------------------
#define NB_X  16384   // conv_x: MROWS*CDIM/(256*4)
#define NB_WQ 3072    // 1536*512/256
#define NB_WO 1024    // 512*512/256
#define NB_RT 16      // 4096/256
#define NB_PREP (NB_X + NB_WQ + NB_WO + NB_RT)

__global__ void prep(const float* __restrict__ x,
                     const float* __restrict__ Wq, const float* __restrict__ Wk,
                     const float* __restrict__ Wv, const float* __restrict__ Wo,
                     __half* __restrict__ hx, __half* __restrict__ bq,
                     __half* __restrict__ bo,
                     float* __restrict__ ct, float* __restrict__ st)
{
    int bid = blockIdx.x;
    int tid = threadIdx.x;
    if (bid < NB_X) {
        size_t i = ((size_t)bid * 256 + tid) * 4;
        float4 v = *(const float4*)(x + i);
        __half h[4];
        h[0] = __float2half_rn(v.x); h[1] = __float2half_rn(v.y);
        h[2] = __float2half_rn(v.z); h[3] = __float2half_rn(v.w);
        *(uint2*)(hx + i) = *(uint2*)h;
    } else if (bid < NB_X + NB_WQ) {
        int idx = (bid - NB_X) * 256 + tid;          // over 1536*512
        int n = idx >> 9, k = idx & 511;
        const float* W = (n < 512) ? Wq : (n < 1024) ? Wk : Wv;
        bq[idx] = __float2half_rn(W[(size_t)k * 512 + (n & 511)]);
    } else if (bid < NB_X + NB_WQ + NB_WO) {
        int idx = (bid - NB_X - NB_WQ) * 256 + tid;  // over 512*512
        int n = idx >> 9, k = idx & 511;
        bo[idx] = __float2half_rn(Wo[(size_t)k * 512 + n]);
    } else {
        int i = (bid - NB_X - NB_WQ - NB_WO) * 256 + tid;   // 4096
        int s = i >> 5, d = i & 31;
        float invf = powf(10000.0f, -(float)d * (1.0f / 32.0f));
        float si, co;
        sincosf((float)s * invf, &si, &co);
        ct[i] = co;
        st[i] = si;
    }
}

// ---------------------------------------------------------------------------
// fp16 GEMM via mma.sync: C = A @ B^T (single-term A).  [R10/R12 configuration]
// Tile 128x256, 256 threads (8 warps of 64x64), Kc=32, 4-stage cp.async
// pipeline, one __syncthreads per chunk, SW64 swizzle, 1 CTA/SM.
// mbase: global row offset (batch-split pipelining).
// QKV=0: f32 row-major out. QKV=1: which=n>>9 -> Cq fp32 | Ck fp16 | Cv fp16.
// ---------------------------------------------------------------------------
#define KC 32
#define CHUNKS 16
#define GA_BYTES (128 * 64)                    // 8192
#define GB_BYTES (256 * 64)                    // 16384
#define STAGE_BYTES (GA_BYTES + GB_BYTES)      // 24576
#define OFF_B   GA_BYTES
#define GSTAGES 4
#define GEMM_SMEM (GSTAGES * STAGE_BYTES)      // 98304

template<int QKV>
__global__ __launch_bounds__(256, 1) void tc_gemm(const __half* __restrict__ Aw,
                                                  const __half* __restrict__ Bw,
                                                  float* __restrict__ Cf,
                                                  float* __restrict__ Cq,
                                                  __half* __restrict__ Ck,
                                                  __half* __restrict__ Cv,
                                                  int mbase)
{
    extern __shared__ __align__(1024) char smv[];
    const uint32_t sb = smem_to_u32(smv);
    const int tid  = threadIdx.x;
    const int wid  = tid >> 5;
    const int lane = tid & 31;
    const int wm   = (wid & 1) * 64;       // 0/64
    const int wn   = (wid >> 1) * 64;      // 0/64/128/192

    const int m0 = mbase + blockIdx.y * 128;
    const int n0 = blockIdx.x * 256;

    float acc[4][8][4];
#pragma unroll
    for (int mi = 0; mi < 4; mi++)
#pragma unroll
        for (int ni = 0; ni < 8; ni++)
#pragma unroll
            for (int v = 0; v < 4; v++) acc[mi][ni][v] = 0.0f;

    auto issue = [&](int c) {
        const uint32_t base = sb + (c % GSTAGES) * STAGE_BYTES;
        const int k0 = c * KC;
#pragma unroll
        for (int r = 0; r < 2; r++) {
            int idx = tid + r * 256;           // 0..511
            int arow = idx >> 2, ach = idx & 3;
            uint32_t off = SWZ64((uint32_t)(arow * 64 + ach * 16));
            size_t ga = (size_t)(m0 + arow) * CDIM + k0 + ach * 8;
            CP_ASYNC16(base + off, Aw + ga);
        }
#pragma unroll
        for (int r = 0; r < 4; r++) {
            int idx = tid + r * 256;           // 0..1023
            int brow = idx >> 2, bch = idx & 3;
            uint32_t off = SWZ64((uint32_t)(brow * 64 + bch * 16));
            size_t gb = (size_t)(n0 + brow) * CDIM + k0 + bch * 8;
            CP_ASYNC16(base + OFF_B + off, Bw + gb);
        }
        CP_COMMIT();
    };

    issue(0); issue(1); issue(2);

    const int lrow = lane & 15;
    const int lkh  = (lane >> 4) * 16;

    for (int c = 0; c < CHUNKS; c++) {
        if (c < CHUNKS - 2)       cp_wait<2>();
        else if (c == CHUNKS - 2) cp_wait<1>();
        else                      cp_wait<0>();
        __syncthreads();
        if (c + 3 < CHUNKS) issue(c + 3);

        const uint32_t base = sb + (c % GSTAGES) * STAGE_BYTES;

        // Preload all fragments for both k16 steps, then dense MMA burst.
        uint32_t af[2][4][4], bfr[2][8][2];
#pragma unroll
        for (int s = 0; s < 2; s++) {
#pragma unroll
            for (int mi = 0; mi < 4; mi++) {
                uint32_t a = SWZ64((uint32_t)((wm + mi * 16 + lrow) * 64 + s * 32 + lkh));
                ldsm4(af[s][mi], base + a);
            }
#pragma unroll
            for (int g = 0; g < 4; g++) {
                uint32_t a = SWZ64((uint32_t)((wn + g * 16 + lrow) * 64 + s * 32 + lkh));
                uint32_t t[4];
                ldsm4(t, base + OFF_B + a);
                bfr[s][g*2][0] = t[0]; bfr[s][g*2+1][0] = t[1];
                bfr[s][g*2][1] = t[2]; bfr[s][g*2+1][1] = t[3];
            }
        }
#pragma unroll
        for (int s = 0; s < 2; s++)
#pragma unroll
            for (int mi = 0; mi < 4; mi++)
#pragma unroll
                for (int ni = 0; ni < 8; ni++)
                    mma2(acc[mi][ni], af[s][mi], bfr[s][ni][0], bfr[s][ni][1]);
    }

    // ---- epilogue ----
#pragma unroll
    for (int mi = 0; mi < 4; mi++) {
        int r = m0 + wm + mi * 16 + (lane >> 2);
#pragma unroll
        for (int ni = 0; ni < 8; ni++) {
            int gn = n0 + wn + ni * 8 + (lane & 3) * 2;
            if (!QKV) {
                size_t dst = (size_t)r * CDIM + gn;
                *(float2*)(Cf + dst) = make_float2(acc[mi][ni][0], acc[mi][ni][1]);
                *(float2*)(Cf + dst + (size_t)8 * CDIM) = make_float2(acc[mi][ni][2], acc[mi][ni][3]);
            } else {
                const int which = gn >> 9;      // uniform per CTA
                const int col = gn & 511;
                size_t dst = (size_t)r * CDIM + col;
                if (which == 0) {
                    *(float2*)(Cq + dst) = make_float2(acc[mi][ni][0], acc[mi][ni][1]);
                    *(float2*)(Cq + dst + (size_t)8 * CDIM) = make_float2(acc[mi][ni][2], acc[mi][ni][3]);
                } else {
                    __half* Cd = (which == 1) ? Ck : Cv;
                    __half2 h0; h0.x = __float2half_rn(acc[mi][ni][0]);
                                h0.y = __float2half_rn(acc[mi][ni][1]);
                    __half2 h1; h1.x = __float2half_rn(acc[mi][ni][2]);
                                h1.y = __float2half_rn(acc[mi][ni][3]);
                    *(__half2*)(Cd + dst) = h0;
                    *(__half2*)(Cd + dst + (size_t)8 * CDIM) = h1;
                }
            }
        }
    }
}

// ---------------------------------------------------------------------------
// HMMA attention: block per (n,h), 8 warps x 16 q-rows. nbase = b*64.
// QK^T: Q hi/lo (from fp32 input) x K single. P·V: P (normalized) x V single.
// RoPE from precomputed tables; staging vectorized.
// ---------------------------------------------------------------------------
#define AT_LD 72
#define AT_ROWB 144
#define AT_TILE (128 * AT_ROWB)     // 18432
#define OFF_QHs 0
#define OFF_QLs (1 * AT_TILE)
#define OFF_KHs (2 * AT_TILE)
#define OFF_VHs (3 * AT_TILE)
#define OFF_MKs (4 * AT_TILE)       // 73728
#define ATT2_SMEM (OFF_MKs + 128)   // 73856

__global__ __launch_bounds__(256, 2) void attn2(const float* __restrict__ Qf,
                                                const __half* __restrict__ Kg,
                                                const __half* __restrict__ Vg,
                                                const unsigned char* __restrict__ pm,
                                                const float* __restrict__ ct,
                                                const float* __restrict__ st,
                                                __half* __restrict__ Oh,
                                                int nbase)
{
    extern __shared__ __align__(1024) char smc[];
    const uint32_t sb = smem_to_u32(smc);
    unsigned char* mk = (unsigned char*)(smc + OFF_MKs);

    const int tid  = threadIdx.x;
    const int lane = tid & 31;
    const int wid  = tid >> 5;
    const int n = nbase + blockIdx.x, h = blockIdx.y;
    const int b = n >> 6, w = n & 63;

    if (tid < 128) mk[tid] = pm[(size_t)b * TTOT + tid * WDIL + w];

    // V tile (single fp16): 128 rows x 8 16B-chunks
    for (int t = tid; t < 1024; t += 256) {
        int row = t >> 3, ch = t & 7;
        size_t g = ((size_t)(b * TTOT + row * WDIL + w)) * CDIM + h * HDIM + ch * 8;
        CP_ASYNC16(sb + OFF_VHs + row * AT_ROWB + ch * 16, Vg + g);
    }
    CP_COMMIT();

    // Q/K staging with table RoPE, vectorized over (s, dd=2d) pairs.
    const float QSCALE = 0.125f * 1.44269504088896f;
    __half* sQh = (__half*)(smc + OFF_QHs);
    __half* sQl = (__half*)(smc + OFF_QLs);
    __half* sKh = (__half*)(smc + OFF_KHs);
    for (int e = tid; e < 128 * 16; e += 256) {
        int s = e >> 4, dd = (e & 15) * 2;
        size_t rb = ((size_t)(b * TTOT + s * WDIL + w)) * CDIM + h * HDIM;
        int te = s * 32 + dd;
        float2 co = *(const float2*)(ct + te);
        float2 si = *(const float2*)(st + te);
        float2 q01 = *(const float2*)(Qf + rb + dd);
        float2 q23 = *(const float2*)(Qf + rb + dd + 32);
        __half2 k01 = *(const __half2*)(Kg + rb + dd);
        __half2 k23 = *(const __half2*)(Kg + rb + dd + 32);
        float qa0 = (q01.x * co.x - q23.x * si.x) * QSCALE;
        float qa1 = (q01.y * co.y - q23.y * si.y) * QSCALE;
        float qb0 = (q23.x * co.x + q01.x * si.x) * QSCALE;
        float qb1 = (q23.y * co.y + q01.y * si.y) * QSCALE;
        __half2 ha, hl;
        ha.x = __float2half_rn(qa0); ha.y = __float2half_rn(qa1);
        hl.x = __float2half_rn(qa0 - __half2float(ha.x));
        hl.y = __float2half_rn(qa1 - __half2float(ha.y));
        *(__half2*)(sQh + s * AT_LD + dd) = ha;
        *(__half2*)(sQl + s * AT_LD + dd) = hl;
        ha.x = __float2half_rn(qb0); ha.y = __float2half_rn(qb1);
        hl.x = __float2half_rn(qb0 - __half2float(ha.x));
        hl.y = __float2half_rn(qb1 - __half2float(ha.y));
        *(__half2*)(sQh + s * AT_LD + dd + 32) = ha;
        *(__half2*)(sQl + s * AT_LD + dd + 32) = hl;
        float k0x = __half2float(k01.x), k0y = __half2float(k01.y);
        float k2x = __half2float(k23.x), k2y = __half2float(k23.y);
        __half2 kk;
        kk.x = __float2half_rn(k0x * co.x - k2x * si.x);
        kk.y = __float2half_rn(k0y * co.y - k2y * si.y);
        *(__half2*)(sKh + s * AT_LD + dd) = kk;
        kk.x = __float2half_rn(k2x * co.x + k0x * si.x);
        kk.y = __float2half_rn(k2y * co.y + k0y * si.y);
        *(__half2*)(sKh + s * AT_LD + dd + 32) = kk;
    }
    cp_wait<0>();
    __syncthreads();

    // ===== QK^T: warp tile m16 x n128 x k64 =====
    const int qr = wid * 16;
    float c[16][4];
#pragma unroll
    for (int j = 0; j < 16; j++)
#pragma unroll
        for (int v = 0; v < 4; v++) c[j][v] = 0.0f;

#pragma unroll
    for (int kk = 0; kk < 4; kk++) {
        uint32_t ah[4], al[4];
        uint32_t abase = sb + OFF_QHs + (uint32_t)((qr + (lane & 15)) * AT_ROWB)
                       + kk * 32 + (lane >> 4) * 16;
        ldsm4(ah, abase);
        ldsm4(al, abase + AT_TILE);
#pragma unroll
        for (int g = 0; g < 8; g++) {
            uint32_t kaddr = sb + OFF_KHs + (uint32_t)((g * 16 + (lane & 15)) * AT_ROWB)
                           + kk * 32 + (lane >> 4) * 16;
            uint32_t th[4];
            ldsm4(th, kaddr);
            mma2(c[2*g],   ah, th[0], th[2]);
            mma2(c[2*g],   al, th[0], th[2]);
            mma2(c[2*g+1], ah, th[1], th[3]);
            mma2(c[2*g+1], al, th[1], th[3]);
        }
    }

    // ===== mask + softmax (normalize P in-place) =====
    float mx0 = -1e30f, mx1 = -1e30f;
#pragma unroll
    for (int j = 0; j < 16; j++) {
        int n0 = j * 8 + (lane & 3) * 2;
        if (mk[n0])     { c[j][0] = -1e30f; c[j][2] = -1e30f; }
        if (mk[n0 + 1]) { c[j][1] = -1e30f; c[j][3] = -1e30f; }
        mx0 = fmaxf(mx0, fmaxf(c[j][0], c[j][1]));
        mx1 = fmaxf(mx1, fmaxf(c[j][2], c[j][3]));
    }
    mx0 = fmaxf(mx0, __shfl_xor_sync(~0u, mx0, 1));
    mx0 = fmaxf(mx0, __shfl_xor_sync(~0u, mx0, 2));
    mx1 = fmaxf(mx1, __shfl_xor_sync(~0u, mx1, 1));
    mx1 = fmaxf(mx1, __shfl_xor_sync(~0u, mx1, 2));
    float s0 = 0.0f, s1 = 0.0f;
#pragma unroll
    for (int j = 0; j < 16; j++) {
        c[j][0] = ex2f(c[j][0] - mx0); s0 += c[j][0];
        c[j][1] = ex2f(c[j][1] - mx0); s0 += c[j][1];
        c[j][2] = ex2f(c[j][2] - mx1); s1 += c[j][2];
        c[j][3] = ex2f(c[j][3] - mx1); s1 += c[j][3];
    }
    s0 += __shfl_xor_sync(~0u, s0, 1); s0 += __shfl_xor_sync(~0u, s0, 2);
    s1 += __shfl_xor_sync(~0u, s1, 1); s1 += __shfl_xor_sync(~0u, s1, 2);
    const float inv0 = 1.0f / s0, inv1 = 1.0f / s1;
#pragma unroll
    for (int j = 0; j < 16; j++) {
        c[j][0] *= inv0; c[j][1] *= inv0;
        c[j][2] *= inv1; c[j][3] *= inv1;
    }

    // ===== P @ V: m16 x n64 x k128 (P normalized fp16, V single) =====
    float o[8][4];
#pragma unroll
    for (int j = 0; j < 8; j++)
#pragma unroll
        for (int v = 0; v < 4; v++) o[j][v] = 0.0f;

#pragma unroll
    for (int t = 0; t < 8; t++) {
        uint32_t pa[4];
#pragma unroll
        for (int q = 0; q < 4; q++) {
            int jt = 2 * t + (q >> 1);
            pa[q] = packh(c[jt][(q & 1) * 2], c[jt][(q & 1) * 2 + 1]);
        }
#pragma unroll
        for (int gg = 0; gg < 4; gg++) {
            uint32_t vaddr = sb + OFF_VHs
                + (uint32_t)((t * 16 + (lane & 7) + ((lane >> 3) & 1) * 8) * AT_ROWB)
                + gg * 32 + (lane >> 4) * 16;
            uint32_t vh[4];
            ldsm4t(vh, vaddr);
            mma2(o[2*gg],   pa, vh[0], vh[1]);
            mma2(o[2*gg+1], pa, vh[2], vh[3]);
        }
    }

    // ===== epilogue: single fp16 store =====
    const int r0 = qr + (lane >> 2);
#pragma unroll
    for (int j2 = 0; j2 < 8; j2++) {
        int d0 = j2 * 8 + (lane & 3) * 2;
        size_t g0 = ((size_t)(b * TTOT + r0 * WDIL + w)) * CDIM + h * HDIM + d0;
        size_t g1 = g0 + (size_t)8 * WDIL * CDIM;
        __half2 hv;
        hv.x = __float2half_rn(o[j2][0]);
        hv.y = __float2half_rn(o[j2][1]);
        *(__half2*)(Oh + g0) = hv;
        hv.x = __float2half_rn(o[j2][2]);
        hv.y = __float2half_rn(o[j2][3]);
        *(__half2*)(Oh + g1) = hv;
    }
}

// ---------------------------------------------------------------------------
// Launch: batch-split two-stream pipeline.
//   NULL stream: prep, QKV(0..3)  (events eq[b] after each QKV)
//   s1:          [wait eq[b]] attn(b), Wo(b);  join back to NULL at end.
// ---------------------------------------------------------------------------
extern "C" void kernel_launch(void* const* d_in, const int* in_sizes, int n_in,
                              void* d_out, int out_size)
{
    const float*         x  = (const float*)d_in[0];
    const unsigned char* pm = (const unsigned char*)d_in[1];
    const float*         Wq = (const float*)d_in[2];
    const float*         Wk = (const float*)d_in[3];
    const float*         Wv = (const float*)d_in[4];
    const float*         Wo = (const float*)d_in[5];
    float*               out = (float*)d_out;

    __half *xh, *kh, *vh, *oh, *bq, *bo;
    float *qf, *ctab, *stab;
    cudaGetSymbolAddress((void**)&xh, g_xh);
    cudaGetSymbolAddress((void**)&qf, g_Qf);
    cudaGetSymbolAddress((void**)&kh, g_Kh);
    cudaGetSymbolAddress((void**)&vh, g_Vh);
    cudaGetSymbolAddress((void**)&oh, g_Oh);
    cudaGetSymbolAddress((void**)&bq, g_Bq);
    cudaGetSymbolAddress((void**)&bo, g_Bo);
    cudaGetSymbolAddress((void**)&ctab, g_cos);
    cudaGetSymbolAddress((void**)&stab, g_sin);

    cudaFuncSetAttribute((const void*)tc_gemm<1>,
                         cudaFuncAttributeMaxDynamicSharedMemorySize, GEMM_SMEM);
    cudaFuncSetAttribute((const void*)tc_gemm<0>,
                         cudaFuncAttributeMaxDynamicSharedMemorySize, GEMM_SMEM);
    cudaFuncSetAttribute(attn2, cudaFuncAttributeMaxDynamicSharedMemorySize, ATT2_SMEM);

    // One-time stream/event setup (host-side resources, reused across calls).
    static cudaStream_t s1 = nullptr;
    static cudaEvent_t  eq[BSZ], ej;
    if (s1 == nullptr) {
        cudaStreamCreateWithFlags(&s1, cudaStreamNonBlocking);
        for (int b = 0; b < BSZ; b++)
            cudaEventCreateWithFlags(&eq[b], cudaEventDisableTiming);
        cudaEventCreateWithFlags(&ej, cudaEventDisableTiming);
    }

    // 1) fused conversions + RoPE tables (NULL stream)
    prep<<<NB_PREP, 256>>>(x, Wq, Wk, Wv, Wo, xh, bq, bo, ctab, stab);

    // 2) per-batch pipeline
    for (int b = 0; b < BSZ; b++) {
        tc_gemm<1><<<dim3(6, BROWS / 128), 256, GEMM_SMEM>>>(
            xh, bq, nullptr, qf, kh, vh, b * BROWS);
        cudaEventRecord(eq[b], 0);

        cudaStreamWaitEvent(s1, eq[b], 0);
        attn2<<<dim3(64, NHEAD), 256, ATT2_SMEM, s1>>>(
            qf, kh, vh, pm, ctab, stab, oh, b * 64);
        tc_gemm<0><<<dim3(2, BROWS / 128), 256, GEMM_SMEM, s1>>>(
            oh, bo, out, nullptr, nullptr, nullptr, b * BROWS);
    }

    // 3) join s1 back into the NULL stream
    cudaEventRecord(ej, s1);
    cudaStreamWaitEvent(0, ej, 0);
}

// round 15
// speedup vs baseline: 1.0568x; 1.0568x over previous
#include <cuda_runtime.h>
#include <cuda_fp16.h>
#include <math.h>
#include <stdint.h>

// Problem constants: B=4, T=8192, C=512, W=64 -> S=128, N=256, heads=8, hd=64
#define BSZ   4
#define TTOT  8192
#define CDIM  512
#define WDIL  64
#define NHEAD 8
#define HDIM  64
#define MROWS (BSZ * TTOT)   // 32768

// ---------------------------------------------------------------------------
// Scratch (static device memory; no allocation allowed)
// ---------------------------------------------------------------------------
__device__ __align__(1024) __half g_xh[(size_t)MROWS * CDIM];      // x fp16
__device__ __align__(1024) __half g_Qh[(size_t)MROWS * CDIM];      // Q fp16
__device__ __align__(1024) __half g_Kh[(size_t)MROWS * CDIM];      // K fp16
__device__ __align__(1024) __half g_Vh[(size_t)MROWS * CDIM];      // V fp16
__device__ __align__(1024) __half g_Oh[(size_t)MROWS * CDIM];      // attn out fp16
__device__ __align__(1024) __half g_Bq[(size_t)3 * CDIM * CDIM];   // QKV W^T [1536,512] K-major
__device__ __align__(1024) __half g_Bo[(size_t)CDIM * CDIM];       // Wo^T [512,512] K-major
__device__ float g_cos[128 * 32];                                  // RoPE tables
__device__ float g_sin[128 * 32];

// ---------------------------------------------------------------------------
// PTX helpers (sm_80-class only: cp.async, ldmatrix, mma.sync)
// ---------------------------------------------------------------------------
__device__ __forceinline__ uint32_t smem_to_u32(const void* p) {
    uint32_t a;
    asm("{ .reg .u64 t; cvta.to.shared.u64 t, %1; cvt.u32.u64 %0, t; }" : "=r"(a) : "l"(p));
    return a;
}
#define CP_ASYNC16(smaddr, gptr) \
    asm volatile("cp.async.cg.shared.global [%0], [%1], 16;" :: "r"(smaddr), "l"(gptr) : "memory")
#define CP_COMMIT() asm volatile("cp.async.commit_group;" ::: "memory")
template <int N> __device__ __forceinline__ void cp_wait() {
    asm volatile("cp.async.wait_group %0;" :: "n"(N) : "memory");
}
__device__ __forceinline__ void ldsm4(uint32_t* r, uint32_t addr) {
    asm volatile("ldmatrix.sync.aligned.m8n8.x4.shared.b16 {%0,%1,%2,%3}, [%4];"
                 : "=r"(r[0]), "=r"(r[1]), "=r"(r[2]), "=r"(r[3]) : "r"(addr));
}
__device__ __forceinline__ void ldsm4t(uint32_t* r, uint32_t addr) {
    asm volatile("ldmatrix.sync.aligned.m8n8.x4.trans.shared.b16 {%0,%1,%2,%3}, [%4];"
                 : "=r"(r[0]), "=r"(r[1]), "=r"(r[2]), "=r"(r[3]) : "r"(addr));
}
__device__ __forceinline__ void mma2(float* d, const uint32_t* a, uint32_t b0, uint32_t b1) {
    asm volatile("mma.sync.aligned.m16n8k16.row.col.f32.f16.f16.f32 "
                 "{%0,%1,%2,%3}, {%4,%5,%6,%7}, {%8,%9}, {%0,%1,%2,%3};"
                 : "+f"(d[0]), "+f"(d[1]), "+f"(d[2]), "+f"(d[3])
                 : "r"(a[0]), "r"(a[1]), "r"(a[2]), "r"(a[3]), "r"(b0), "r"(b1));
}
__device__ __forceinline__ float ex2f(float x) {
    float y; asm("ex2.approx.ftz.f32 %0, %1;" : "=f"(y) : "f"(x)); return y;
}
__device__ __forceinline__ uint32_t packh(float x, float y) {
    __half2 t = __floats2half2_rn(x, y);
    return *(uint32_t*)&t;
}
#define SWZ64(off) ((off) ^ (((off) >> 3) & 0x30))

// ---------------------------------------------------------------------------
// Fused prep kernel: conv_x | conv_wqkv | conv_wo | rope tables, one launch.
// ---------------------------------------------------------------------------
#define NB_X  16384   // conv_x: MROWS*CDIM/(256*4)
#define NB_WQ 3072    // 1536*512/256
#define NB_WO 1024    // 512*512/256
#define NB_RT 16      // 4096/256
#define NB_PREP (NB_X + NB_WQ + NB_WO + NB_RT)

__global__ void prep(const float* __restrict__ x,
                     const float* __restrict__ Wq, const float* __restrict__ Wk,
                     const float* __restrict__ Wv, const float* __restrict__ Wo,
                     __half* __restrict__ hx, __half* __restrict__ bq,
                     __half* __restrict__ bo,
                     float* __restrict__ ct, float* __restrict__ st)
{
    int bid = blockIdx.x;
    int tid = threadIdx.x;
    if (bid < NB_X) {
        size_t i = ((size_t)bid * 256 + tid) * 4;
        float4 v = *(const float4*)(x + i);
        __half h[4];
        h[0] = __float2half_rn(v.x); h[1] = __float2half_rn(v.y);
        h[2] = __float2half_rn(v.z); h[3] = __float2half_rn(v.w);
        *(uint2*)(hx + i) = *(uint2*)h;
    } else if (bid < NB_X + NB_WQ) {
        int idx = (bid - NB_X) * 256 + tid;          // over 1536*512
        int n = idx >> 9, k = idx & 511;
        const float* W = (n < 512) ? Wq : (n < 1024) ? Wk : Wv;
        bq[idx] = __float2half_rn(W[(size_t)k * 512 + (n & 511)]);
    } else if (bid < NB_X + NB_WQ + NB_WO) {
        int idx = (bid - NB_X - NB_WQ) * 256 + tid;  // over 512*512
        int n = idx >> 9, k = idx & 511;
        bo[idx] = __float2half_rn(Wo[(size_t)k * 512 + n]);
    } else {
        int i = (bid - NB_X - NB_WQ - NB_WO) * 256 + tid;   // 4096
        int s = i >> 5, d = i & 31;
        float invf = powf(10000.0f, -(float)d * (1.0f / 32.0f));
        float si, co;
        sincosf((float)s * invf, &si, &co);
        ct[i] = co;
        st[i] = si;
    }
}

// ---------------------------------------------------------------------------
// fp16 GEMM via mma.sync: C = A @ B^T (single-term A).  [R10/R13 mainloop]
// Tile 128x256, 256 threads (8 warps of 64x64), Kc=32, 4-stage cp.async
// pipeline, one __syncthreads per chunk, SW64 swizzle, 1 CTA/SM.
// QKV=0: f32 row-major out. QKV=1: which=n>>9 -> Cq | Ck | Cv, all fp16.
// ---------------------------------------------------------------------------
#define KC 32
#define CHUNKS 16
#define GA_BYTES (128 * 64)                    // 8192
#define GB_BYTES (256 * 64)                    // 16384
#define STAGE_BYTES (GA_BYTES + GB_BYTES)      // 24576
#define OFF_B   GA_BYTES
#define GSTAGES 4
#define GEMM_SMEM (GSTAGES * STAGE_BYTES)      // 98304

template<int QKV>
__global__ __launch_bounds__(256, 1) void tc_gemm(const __half* __restrict__ Aw,
                                                  const __half* __restrict__ Bw,
                                                  float* __restrict__ Cf,
                                                  __half* __restrict__ Cq,
                                                  __half* __restrict__ Ck,
                                                  __half* __restrict__ Cv)
{
    extern __shared__ __align__(1024) char smv[];
    const uint32_t sb = smem_to_u32(smv);
    const int tid  = threadIdx.x;
    const int wid  = tid >> 5;
    const int lane = tid & 31;
    const int wm   = (wid & 1) * 64;       // 0/64
    const int wn   = (wid >> 1) * 64;      // 0/64/128/192

    const int m0 = blockIdx.y * 128;
    const int n0 = blockIdx.x * 256;

    float acc[4][8][4];
#pragma unroll
    for (int mi = 0; mi < 4; mi++)
#pragma unroll
        for (int ni = 0; ni < 8; ni++)
#pragma unroll
            for (int v = 0; v < 4; v++) acc[mi][ni][v] = 0.0f;

    auto issue = [&](int c) {
        const uint32_t base = sb + (c % GSTAGES) * STAGE_BYTES;
        const int k0 = c * KC;
#pragma unroll
        for (int r = 0; r < 2; r++) {
            int idx = tid + r * 256;           // 0..511
            int arow = idx >> 2, ach = idx & 3;
            uint32_t off = SWZ64((uint32_t)(arow * 64 + ach * 16));
            size_t ga = (size_t)(m0 + arow) * CDIM + k0 + ach * 8;
            CP_ASYNC16(base + off, Aw + ga);
        }
#pragma unroll
        for (int r = 0; r < 4; r++) {
            int idx = tid + r * 256;           // 0..1023
            int brow = idx >> 2, bch = idx & 3;
            uint32_t off = SWZ64((uint32_t)(brow * 64 + bch * 16));
            size_t gb = (size_t)(n0 + brow) * CDIM + k0 + bch * 8;
            CP_ASYNC16(base + OFF_B + off, Bw + gb);
        }
        CP_COMMIT();
    };

    issue(0); issue(1); issue(2);

    const int lrow = lane & 15;
    const int lkh  = (lane >> 4) * 16;

    for (int c = 0; c < CHUNKS; c++) {
        if (c < CHUNKS - 2)       cp_wait<2>();
        else if (c == CHUNKS - 2) cp_wait<1>();
        else                      cp_wait<0>();
        __syncthreads();
        if (c + 3 < CHUNKS) issue(c + 3);

        const uint32_t base = sb + (c % GSTAGES) * STAGE_BYTES;

        // Preload all fragments for both k16 steps, then dense MMA burst.
        uint32_t af[2][4][4], bfr[2][8][2];
#pragma unroll
        for (int s = 0; s < 2; s++) {
#pragma unroll
            for (int mi = 0; mi < 4; mi++) {
                uint32_t a = SWZ64((uint32_t)((wm + mi * 16 + lrow) * 64 + s * 32 + lkh));
                ldsm4(af[s][mi], base + a);
            }
#pragma unroll
            for (int g = 0; g < 4; g++) {
                uint32_t a = SWZ64((uint32_t)((wn + g * 16 + lrow) * 64 + s * 32 + lkh));
                uint32_t t[4];
                ldsm4(t, base + OFF_B + a);
                bfr[s][g*2][0] = t[0]; bfr[s][g*2+1][0] = t[1];
                bfr[s][g*2][1] = t[2]; bfr[s][g*2+1][1] = t[3];
            }
        }
#pragma unroll
        for (int s = 0; s < 2; s++)
#pragma unroll
            for (int mi = 0; mi < 4; mi++)
#pragma unroll
                for (int ni = 0; ni < 8; ni++)
                    mma2(acc[mi][ni], af[s][mi], bfr[s][ni][0], bfr[s][ni][1]);
    }

    // ---- epilogue ----
#pragma unroll
    for (int mi = 0; mi < 4; mi++) {
        int r = m0 + wm + mi * 16 + (lane >> 2);
#pragma unroll
        for (int ni = 0; ni < 8; ni++) {
            int gn = n0 + wn + ni * 8 + (lane & 3) * 2;
            if (!QKV) {
                size_t dst = (size_t)r * CDIM + gn;
                *(float2*)(Cf + dst) = make_float2(acc[mi][ni][0], acc[mi][ni][1]);
                *(float2*)(Cf + dst + (size_t)8 * CDIM) = make_float2(acc[mi][ni][2], acc[mi][ni][3]);
            } else {
                const int which = gn >> 9;      // uniform per CTA
                const int col = gn & 511;
                size_t dst = (size_t)r * CDIM + col;
                __half* Cd = (which == 0) ? Cq : (which == 1) ? Ck : Cv;
                __half2 h0; h0.x = __float2half_rn(acc[mi][ni][0]);
                            h0.y = __float2half_rn(acc[mi][ni][1]);
                __half2 h1; h1.x = __float2half_rn(acc[mi][ni][2]);
                            h1.y = __float2half_rn(acc[mi][ni][3]);
                *(__half2*)(Cd + dst) = h0;
                *(__half2*)(Cd + dst + (size_t)8 * CDIM) = h1;
            }
        }
    }
}

// ---------------------------------------------------------------------------
// HMMA attention: block per (n,h), 8 warps x 16 q-rows.
// QK^T: Q single x K single. P·V: P (normalized) x V single.
// RoPE from precomputed tables; staging vectorized (half2).
// Smem: 3 tiles (Q, K, V) + mask = ~55KB -> 2 CTAs/SM.
// ---------------------------------------------------------------------------
#define AT_LD 72
#define AT_ROWB 144
#define AT_TILE (128 * AT_ROWB)     // 18432
#define OFF_QHs 0
#define OFF_KHs (1 * AT_TILE)
#define OFF_VHs (2 * AT_TILE)
#define OFF_MKs (3 * AT_TILE)       // 55296
#define ATT2_SMEM (OFF_MKs + 128)   // 55424

__global__ __launch_bounds__(256, 2) void attn2(const __half* __restrict__ Qg,
                                                const __half* __restrict__ Kg,
                                                const __half* __restrict__ Vg,
                                                const unsigned char* __restrict__ pm,
                                                const float* __restrict__ ct,
                                                const float* __restrict__ st,
                                                __half* __restrict__ Oh)
{
    extern __shared__ __align__(1024) char smc[];
    const uint32_t sb = smem_to_u32(smc);
    unsigned char* mk = (unsigned char*)(smc + OFF_MKs);

    const int tid  = threadIdx.x;
    const int lane = tid & 31;
    const int wid  = tid >> 5;
    const int n = blockIdx.x, h = blockIdx.y;
    const int b = n >> 6, w = n & 63;

    if (tid < 128) mk[tid] = pm[(size_t)b * TTOT + tid * WDIL + w];

    // V tile (single fp16): 128 rows x 8 16B-chunks
    for (int t = tid; t < 1024; t += 256) {
        int row = t >> 3, ch = t & 7;
        size_t g = ((size_t)(b * TTOT + row * WDIL + w)) * CDIM + h * HDIM + ch * 8;
        CP_ASYNC16(sb + OFF_VHs + row * AT_ROWB + ch * 16, Vg + g);
    }
    CP_COMMIT();

    // Q/K staging with table RoPE, vectorized over (s, dd=2d) pairs.
    const float QSCALE = 0.125f * 1.44269504088896f;
    __half* sQh = (__half*)(smc + OFF_QHs);
    __half* sKh = (__half*)(smc + OFF_KHs);
    for (int e = tid; e < 128 * 16; e += 256) {
        int s = e >> 4, dd = (e & 15) * 2;
        size_t rb = ((size_t)(b * TTOT + s * WDIL + w)) * CDIM + h * HDIM;
        int te = s * 32 + dd;
        float2 co = *(const float2*)(ct + te);
        float2 si = *(const float2*)(st + te);
        __half2 q01h = *(const __half2*)(Qg + rb + dd);
        __half2 q23h = *(const __half2*)(Qg + rb + dd + 32);
        __half2 k01 = *(const __half2*)(Kg + rb + dd);
        __half2 k23 = *(const __half2*)(Kg + rb + dd + 32);
        float q0x = __half2float(q01h.x), q0y = __half2float(q01h.y);
        float q2x = __half2float(q23h.x), q2y = __half2float(q23h.y);
        __half2 qq;
        qq.x = __float2half_rn((q0x * co.x - q2x * si.x) * QSCALE);
        qq.y = __float2half_rn((q0y * co.y - q2y * si.y) * QSCALE);
        *(__half2*)(sQh + s * AT_LD + dd) = qq;
        qq.x = __float2half_rn((q2x * co.x + q0x * si.x) * QSCALE);
        qq.y = __float2half_rn((q2y * co.y + q0y * si.y) * QSCALE);
        *(__half2*)(sQh + s * AT_LD + dd + 32) = qq;
        float k0x = __half2float(k01.x), k0y = __half2float(k01.y);
        float k2x = __half2float(k23.x), k2y = __half2float(k23.y);
        __half2 kk;
        kk.x = __float2half_rn(k0x * co.x - k2x * si.x);
        kk.y = __float2half_rn(k0y * co.y - k2y * si.y);
        *(__half2*)(sKh + s * AT_LD + dd) = kk;
        kk.x = __float2half_rn(k2x * co.x + k0x * si.x);
        kk.y = __float2half_rn(k2y * co.y + k0y * si.y);
        *(__half2*)(sKh + s * AT_LD + dd + 32) = kk;
    }
    cp_wait<0>();
    __syncthreads();

    // ===== QK^T: warp tile m16 x n128 x k64 (Q single) =====
    const int qr = wid * 16;
    float c[16][4];
#pragma unroll
    for (int j = 0; j < 16; j++)
#pragma unroll
        for (int v = 0; v < 4; v++) c[j][v] = 0.0f;

#pragma unroll
    for (int kk = 0; kk < 4; kk++) {
        uint32_t ah[4];
        uint32_t abase = sb + OFF_QHs + (uint32_t)((qr + (lane & 15)) * AT_ROWB)
                       + kk * 32 + (lane >> 4) * 16;
        ldsm4(ah, abase);
#pragma unroll
        for (int g = 0; g < 8; g++) {
            uint32_t kaddr = sb + OFF_KHs + (uint32_t)((g * 16 + (lane & 15)) * AT_ROWB)
                           + kk * 32 + (lane >> 4) * 16;
            uint32_t th[4];
            ldsm4(th, kaddr);
            mma2(c[2*g],   ah, th[0], th[2]);
            mma2(c[2*g+1], ah, th[1], th[3]);
        }
    }

    // ===== mask + softmax (normalize P in-place) =====
    float mx0 = -1e30f, mx1 = -1e30f;
#pragma unroll
    for (int j = 0; j < 16; j++) {
        int n0 = j * 8 + (lane & 3) * 2;
        if (mk[n0])     { c[j][0] = -1e30f; c[j][2] = -1e30f; }
        if (mk[n0 + 1]) { c[j][1] = -1e30f; c[j][3] = -1e30f; }
        mx0 = fmaxf(mx0, fmaxf(c[j][0], c[j][1]));
        mx1 = fmaxf(mx1, fmaxf(c[j][2], c[j][3]));
    }
    mx0 = fmaxf(mx0, __shfl_xor_sync(~0u, mx0, 1));
    mx0 = fmaxf(mx0, __shfl_xor_sync(~0u, mx0, 2));
    mx1 = fmaxf(mx1, __shfl_xor_sync(~0u, mx1, 1));
    mx1 = fmaxf(mx1, __shfl_xor_sync(~0u, mx1, 2));
    float s0 = 0.0f, s1 = 0.0f;
#pragma unroll
    for (int j = 0; j < 16; j++) {
        c[j][0] = ex2f(c[j][0] - mx0); s0 += c[j][0];
        c[j][1] = ex2f(c[j][1] - mx0); s0 += c[j][1];
        c[j][2] = ex2f(c[j][2] - mx1); s1 += c[j][2];
        c[j][3] = ex2f(c[j][3] - mx1); s1 += c[j][3];
    }
    s0 += __shfl_xor_sync(~0u, s0, 1); s0 += __shfl_xor_sync(~0u, s0, 2);
    s1 += __shfl_xor_sync(~0u, s1, 1); s1 += __shfl_xor_sync(~0u, s1, 2);
    const float inv0 = 1.0f / s0, inv1 = 1.0f / s1;
#pragma unroll
    for (int j = 0; j < 16; j++) {
        c[j][0] *= inv0; c[j][1] *= inv0;
        c[j][2] *= inv1; c[j][3] *= inv1;
    }

    // ===== P @ V: m16 x n64 x k128 (P normalized fp16, V single) =====
    float o[8][4];
#pragma unroll
    for (int j = 0; j < 8; j++)
#pragma unroll
        for (int v = 0; v < 4; v++) o[j][v] = 0.0f;

#pragma unroll
    for (int t = 0; t < 8; t++) {
        uint32_t pa[4];
#pragma unroll
        for (int q = 0; q < 4; q++) {
            int jt = 2 * t + (q >> 1);
            pa[q] = packh(c[jt][(q & 1) * 2], c[jt][(q & 1) * 2 + 1]);
        }
#pragma unroll
        for (int gg = 0; gg < 4; gg++) {
            uint32_t vaddr = sb + OFF_VHs
                + (uint32_t)((t * 16 + (lane & 7) + ((lane >> 3) & 1) * 8) * AT_ROWB)
                + gg * 32 + (lane >> 4) * 16;
            uint32_t vh[4];
            ldsm4t(vh, vaddr);
            mma2(o[2*gg],   pa, vh[0], vh[1]);
            mma2(o[2*gg+1], pa, vh[2], vh[3]);
        }
    }

    // ===== epilogue: single fp16 store =====
    const int r0 = qr + (lane >> 2);
#pragma unroll
    for (int j2 = 0; j2 < 8; j2++) {
        int d0 = j2 * 8 + (lane & 3) * 2;
        size_t g0 = ((size_t)(b * TTOT + r0 * WDIL + w)) * CDIM + h * HDIM + d0;
        size_t g1 = g0 + (size_t)8 * WDIL * CDIM;
        __half2 hv;
        hv.x = __float2half_rn(o[j2][0]);
        hv.y = __float2half_rn(o[j2][1]);
        *(__half2*)(Oh + g0) = hv;
        hv.x = __float2half_rn(o[j2][2]);
        hv.y = __float2half_rn(o[j2][3]);
        *(__half2*)(Oh + g1) = hv;
    }
}

// ---------------------------------------------------------------------------
// Launch (serial, NULL stream — R13 skeleton)
// ---------------------------------------------------------------------------
extern "C" void kernel_launch(void* const* d_in, const int* in_sizes, int n_in,
                              void* d_out, int out_size)
{
    const float*         x  = (const float*)d_in[0];
    const unsigned char* pm = (const unsigned char*)d_in[1];
    const float*         Wq = (const float*)d_in[2];
    const float*         Wk = (const float*)d_in[3];
    const float*         Wv = (const float*)d_in[4];
    const float*         Wo = (const float*)d_in[5];
    float*               out = (float*)d_out;

    __half *xh, *qh, *kh, *vh, *oh, *bq, *bo;
    float *ctab, *stab;
    cudaGetSymbolAddress((void**)&xh, g_xh);
    cudaGetSymbolAddress((void**)&qh, g_Qh);
    cudaGetSymbolAddress((void**)&kh, g_Kh);
    cudaGetSymbolAddress((void**)&vh, g_Vh);
    cudaGetSymbolAddress((void**)&oh, g_Oh);
    cudaGetSymbolAddress((void**)&bq, g_Bq);
    cudaGetSymbolAddress((void**)&bo, g_Bo);
    cudaGetSymbolAddress((void**)&ctab, g_cos);
    cudaGetSymbolAddress((void**)&stab, g_sin);

    cudaFuncSetAttribute((const void*)tc_gemm<1>,
                         cudaFuncAttributeMaxDynamicSharedMemorySize, GEMM_SMEM);
    cudaFuncSetAttribute((const void*)tc_gemm<0>,
                         cudaFuncAttributeMaxDynamicSharedMemorySize, GEMM_SMEM);
    cudaFuncSetAttribute(attn2, cudaFuncAttributeMaxDynamicSharedMemorySize, ATT2_SMEM);

    // 1) fused conversions + RoPE tables (one launch)
    prep<<<NB_PREP, 256>>>(x, Wq, Wk, Wv, Wo, xh, bq, bo, ctab, stab);

    // 2) fused QKV projection -> Q | K | V, all fp16
    tc_gemm<1><<<dim3(6, MROWS / 128), 256, GEMM_SMEM>>>(xh, bq,
                                                         nullptr, qh, kh, vh);

    // 3) HMMA attention -> O fp16
    attn2<<<dim3(256, NHEAD), 256, ATT2_SMEM>>>(qh, kh, vh, pm, ctab, stab, oh);

    // 4) output projection (single-term A = Oh) -> d_out (f32)
    tc_gemm<0><<<dim3(2, MROWS / 128), 256, GEMM_SMEM>>>(oh, bo,
                                                         out, nullptr, nullptr, nullptr);
}

// round 16
// speedup vs baseline: 1.1251x; 1.0647x over previous
#include <cuda_runtime.h>
#include <cuda_fp16.h>
#include <math.h>
#include <stdint.h>

// Problem constants: B=4, T=8192, C=512, W=64 -> S=128, N=256, heads=8, hd=64
#define BSZ   4
#define TTOT  8192
#define CDIM  512
#define WDIL  64
#define NHEAD 8
#define HDIM  64
#define MROWS (BSZ * TTOT)   // 32768

// ---------------------------------------------------------------------------
// Scratch (static device memory; no allocation allowed)
// ---------------------------------------------------------------------------
__device__ __align__(1024) __half g_xh[(size_t)MROWS * CDIM];      // x fp16
__device__ __align__(1024) __half g_Qh[(size_t)MROWS * CDIM];      // Q fp16 (RoPE+scale applied)
__device__ __align__(1024) __half g_Kh[(size_t)MROWS * CDIM];      // K fp16 (RoPE applied)
__device__ __align__(1024) __half g_Vh[(size_t)MROWS * CDIM];      // V fp16
__device__ __align__(1024) __half g_Oh[(size_t)MROWS * CDIM];      // attn out fp16
__device__ __align__(1024) __half g_Bq[(size_t)3 * CDIM * CDIM];   // QKV W^T [1536,512] K-major
__device__ __align__(1024) __half g_Bo[(size_t)CDIM * CDIM];       // Wo^T [512,512] K-major
__device__ float g_cos[128 * 32];                                  // RoPE tables
__device__ float g_sin[128 * 32];

#define QSCALE_F (0.125f * 1.44269504088896f)

// ---------------------------------------------------------------------------
// PTX helpers (sm_80-class only: cp.async, ldmatrix, mma.sync)
// ---------------------------------------------------------------------------
__device__ __forceinline__ uint32_t smem_to_u32(const void* p) {
    uint32_t a;
    asm("{ .reg .u64 t; cvta.to.shared.u64 t, %1; cvt.u32.u64 %0, t; }" : "=r"(a) : "l"(p));
    return a;
}
#define CP_ASYNC16(smaddr, gptr) \
    asm volatile("cp.async.cg.shared.global [%0], [%1], 16;" :: "r"(smaddr), "l"(gptr) : "memory")
#define CP_COMMIT() asm volatile("cp.async.commit_group;" ::: "memory")
template <int N> __device__ __forceinline__ void cp_wait() {
    asm volatile("cp.async.wait_group %0;" :: "n"(N) : "memory");
}
__device__ __forceinline__ void ldsm4(uint32_t* r, uint32_t addr) {
    asm volatile("ldmatrix.sync.aligned.m8n8.x4.shared.b16 {%0,%1,%2,%3}, [%4];"
                 : "=r"(r[0]), "=r"(r[1]), "=r"(r[2]), "=r"(r[3]) : "r"(addr));
}
__device__ __forceinline__ void ldsm4t(uint32_t* r, uint32_t addr) {
    asm volatile("ldmatrix.sync.aligned.m8n8.x4.trans.shared.b16 {%0,%1,%2,%3}, [%4];"
                 : "=r"(r[0]), "=r"(r[1]), "=r"(r[2]), "=r"(r[3]) : "r"(addr));
}
__device__ __forceinline__ void mma2(float* d, const uint32_t* a, uint32_t b0, uint32_t b1) {
    asm volatile("mma.sync.aligned.m16n8k16.row.col.f32.f16.f16.f32 "
                 "{%0,%1,%2,%3}, {%4,%5,%6,%7}, {%8,%9}, {%0,%1,%2,%3};"
                 : "+f"(d[0]), "+f"(d[1]), "+f"(d[2]), "+f"(d[3])
                 : "r"(a[0]), "r"(a[1]), "r"(a[2]), "r"(a[3]), "r"(b0), "r"(b1));
}
__device__ __forceinline__ float ex2f(float x) {
    float y; asm("ex2.approx.ftz.f32 %0, %1;" : "=f"(y) : "f"(x)); return y;
}
__device__ __forceinline__ uint32_t packh(float x, float y) {
    __half2 t = __floats2half2_rn(x, y);
    return *(uint32_t*)&t;
}
#define SWZ64(off) ((off) ^ (((off) >> 3) & 0x30))

// ---------------------------------------------------------------------------
// Fused prep kernel: conv_x | conv_wqkv | conv_wo | rope tables, one launch.
// ---------------------------------------------------------------------------
#define NB_X  16384   // conv_x: MROWS*CDIM/(256*4)
#define NB_WQ 3072    // 1536*512/256
#define NB_WO 1024    // 512*512/256
#define NB_RT 16      // 4096/256
#define NB_PREP (NB_X + NB_WQ + NB_WO + NB_RT)

__global__ void prep(const float* __restrict__ x,
                     const float* __restrict__ Wq, const float* __restrict__ Wk,
                     const float* __restrict__ Wv, const float* __restrict__ Wo,
                     __half* __restrict__ hx, __half* __restrict__ bq,
                     __half* __restrict__ bo,
                     float* __restrict__ ct, float* __restrict__ st)
{
    int bid = blockIdx.x;
    int tid = threadIdx.x;
    if (bid < NB_X) {
        size_t i = ((size_t)bid * 256 + tid) * 4;
        float4 v = *(const float4*)(x + i);
        __half h[4];
        h[0] = __float2half_rn(v.x); h[1] = __float2half_rn(v.y);
        h[2] = __float2half_rn(v.z); h[3] = __float2half_rn(v.w);
        *(uint2*)(hx + i) = *(uint2*)h;
    } else if (bid < NB_X + NB_WQ) {
        int idx = (bid - NB_X) * 256 + tid;          // over 1536*512
        int n = idx >> 9, k = idx & 511;
        const float* W = (n < 512) ? Wq : (n < 1024) ? Wk : Wv;
        bq[idx] = __float2half_rn(W[(size_t)k * 512 + (n & 511)]);
    } else if (bid < NB_X + NB_WQ + NB_WO) {
        int idx = (bid - NB_X - NB_WQ) * 256 + tid;  // over 512*512
        int n = idx >> 9, k = idx & 511;
        bo[idx] = __float2half_rn(Wo[(size_t)k * 512 + n]);
    } else {
        int i = (bid - NB_X - NB_WQ - NB_WO) * 256 + tid;   // 4096
        int s = i >> 5, d = i & 31;
        float invf = powf(10000.0f, -(float)d * (1.0f / 32.0f));
        float si, co;
        sincosf((float)s * invf, &si, &co);
        ct[i] = co;
        st[i] = si;
    }
}

// ---------------------------------------------------------------------------
// fp16 GEMM via mma.sync: C = A @ B^T (single-term A).
// Tile 128x256, 256 threads (8 warps of 64x64), Kc=32, 4-stage cp.async
// pipeline, one __syncthreads per chunk, SW64 swizzle, 1 CTA/SM.
// QKV=0: f32 row-major out (Wo projection).
// QKV=1: which=(n0+wn)>>9 -> Cq | Ck | Cv fp16; RoPE (+QSCALE for Q) fused
//        into the epilogue for Q/K partitions. Warp M-tile rows all share the
//        same subsequence position s=((m0+wm)>>6)&127; RoPE pair (d,d+32)
//        maps to fragment pair (ni, ni+4) within the same thread.
// ---------------------------------------------------------------------------
#define KC 32
#define CHUNKS 16
#define GA_BYTES (128 * 64)                    // 8192
#define GB_BYTES (256 * 64)                    // 16384
#define STAGE_BYTES (GA_BYTES + GB_BYTES)      // 24576
#define OFF_B   GA_BYTES
#define GSTAGES 4
#define GEMM_SMEM (GSTAGES * STAGE_BYTES)      // 98304

template<int QKV>
__global__ __launch_bounds__(256, 1) void tc_gemm(const __half* __restrict__ Aw,
                                                  const __half* __restrict__ Bw,
                                                  float* __restrict__ Cf,
                                                  __half* __restrict__ Cq,
                                                  __half* __restrict__ Ck,
                                                  __half* __restrict__ Cv,
                                                  const float* __restrict__ ct,
                                                  const float* __restrict__ st)
{
    extern __shared__ __align__(1024) char smv[];
    const uint32_t sb = smem_to_u32(smv);
    const int tid  = threadIdx.x;
    const int wid  = tid >> 5;
    const int lane = tid & 31;
    const int wm   = (wid & 1) * 64;       // 0/64
    const int wn   = (wid >> 1) * 64;      // 0/64/128/192

    const int m0 = blockIdx.y * 128;
    const int n0 = blockIdx.x * 256;

    float acc[4][8][4];
#pragma unroll
    for (int mi = 0; mi < 4; mi++)
#pragma unroll
        for (int ni = 0; ni < 8; ni++)
#pragma unroll
            for (int v = 0; v < 4; v++) acc[mi][ni][v] = 0.0f;

    auto issue = [&](int c) {
        const uint32_t base = sb + (c % GSTAGES) * STAGE_BYTES;
        const int k0 = c * KC;
#pragma unroll
        for (int r = 0; r < 2; r++) {
            int idx = tid + r * 256;           // 0..511
            int arow = idx >> 2, ach = idx & 3;
            uint32_t off = SWZ64((uint32_t)(arow * 64 + ach * 16));
            size_t ga = (size_t)(m0 + arow) * CDIM + k0 + ach * 8;
            CP_ASYNC16(base + off, Aw + ga);
        }
#pragma unroll
        for (int r = 0; r < 4; r++) {
            int idx = tid + r * 256;           // 0..1023
            int brow = idx >> 2, bch = idx & 3;
            uint32_t off = SWZ64((uint32_t)(brow * 64 + bch * 16));
            size_t gb = (size_t)(n0 + brow) * CDIM + k0 + bch * 8;
            CP_ASYNC16(base + OFF_B + off, Bw + gb);
        }
        CP_COMMIT();
    };

    issue(0); issue(1); issue(2);

    const int lrow = lane & 15;
    const int lkh  = (lane >> 4) * 16;

    for (int c = 0; c < CHUNKS; c++) {
        if (c < CHUNKS - 2)       cp_wait<2>();
        else if (c == CHUNKS - 2) cp_wait<1>();
        else                      cp_wait<0>();
        __syncthreads();
        if (c + 3 < CHUNKS) issue(c + 3);

        const uint32_t base = sb + (c % GSTAGES) * STAGE_BYTES;

        // Preload all fragments for both k16 steps, then dense MMA burst.
        uint32_t af[2][4][4], bfr[2][8][2];
#pragma unroll
        for (int s = 0; s < 2; s++) {
#pragma unroll
            for (int mi = 0; mi < 4; mi++) {
                uint32_t a = SWZ64((uint32_t)((wm + mi * 16 + lrow) * 64 + s * 32 + lkh));
                ldsm4(af[s][mi], base + a);
            }
#pragma unroll
            for (int g = 0; g < 4; g++) {
                uint32_t a = SWZ64((uint32_t)((wn + g * 16 + lrow) * 64 + s * 32 + lkh));
                uint32_t t[4];
                ldsm4(t, base + OFF_B + a);
                bfr[s][g*2][0] = t[0]; bfr[s][g*2+1][0] = t[1];
                bfr[s][g*2][1] = t[2]; bfr[s][g*2+1][1] = t[3];
            }
        }
#pragma unroll
        for (int s = 0; s < 2; s++)
#pragma unroll
            for (int mi = 0; mi < 4; mi++)
#pragma unroll
                for (int ni = 0; ni < 8; ni++)
                    mma2(acc[mi][ni], af[s][mi], bfr[s][ni][0], bfr[s][ni][1]);
    }

    // ---- epilogue ----
    if (!QKV) {
#pragma unroll
        for (int mi = 0; mi < 4; mi++) {
            int r = m0 + wm + mi * 16 + (lane >> 2);
#pragma unroll
            for (int ni = 0; ni < 8; ni++) {
                int gn = n0 + wn + ni * 8 + (lane & 3) * 2;
                size_t dst = (size_t)r * CDIM + gn;
                *(float2*)(Cf + dst) = make_float2(acc[mi][ni][0], acc[mi][ni][1]);
                *(float2*)(Cf + dst + (size_t)8 * CDIM) = make_float2(acc[mi][ni][2], acc[mi][ni][3]);
            }
        }
    } else {
        const int which = (n0 + wn) >> 9;   // warp-uniform partition id
        if (which <= 1) {
            // Q or K: fused RoPE (Q additionally scaled by QSCALE).
            __half* Cd = (which == 0) ? Cq : Ck;
            const float qs = (which == 0) ? QSCALE_F : 1.0f;
            const int srow = ((m0 + wm) >> 6) & 127;   // warp-uniform
#pragma unroll
            for (int mi = 0; mi < 4; mi++) {
                int r = m0 + wm + mi * 16 + (lane >> 2);
#pragma unroll
                for (int ni = 0; ni < 4; ni++) {
                    int d = ni * 8 + (lane & 3) * 2;   // 0..30
                    float co0 = ct[srow * 32 + d],     si0 = st[srow * 32 + d];
                    float co1 = ct[srow * 32 + d + 1], si1 = st[srow * 32 + d + 1];
                    int collo = ((n0 + wn) & 511) + d;
                    size_t dlo = (size_t)r * CDIM + collo;
                    float a0 = acc[mi][ni][0],   a1 = acc[mi][ni][1];
                    float a2 = acc[mi][ni][2],   a3 = acc[mi][ni][3];
                    float b0 = acc[mi][ni+4][0], b1 = acc[mi][ni+4][1];
                    float b2 = acc[mi][ni+4][2], b3 = acc[mi][ni+4][3];
                    __half2 v;
                    v.x = __float2half_rn((a0 * co0 - b0 * si0) * qs);
                    v.y = __float2half_rn((a1 * co1 - b1 * si1) * qs);
                    *(__half2*)(Cd + dlo) = v;
                    v.x = __float2half_rn((b0 * co0 + a0 * si0) * qs);
                    v.y = __float2half_rn((b1 * co1 + a1 * si1) * qs);
                    *(__half2*)(Cd + dlo + 32) = v;
                    size_t dlo8 = dlo + (size_t)8 * CDIM;
                    v.x = __float2half_rn((a2 * co0 - b2 * si0) * qs);
                    v.y = __float2half_rn((a3 * co1 - b3 * si1) * qs);
                    *(__half2*)(Cd + dlo8) = v;
                    v.x = __float2half_rn((b2 * co0 + a2 * si0) * qs);
                    v.y = __float2half_rn((b3 * co1 + a3 * si1) * qs);
                    *(__half2*)(Cd + dlo8 + 32) = v;
                }
            }
        } else {
            // V: plain fp16 store.
#pragma unroll
            for (int mi = 0; mi < 4; mi++) {
                int r = m0 + wm + mi * 16 + (lane >> 2);
#pragma unroll
                for (int ni = 0; ni < 8; ni++) {
                    int gn = n0 + wn + ni * 8 + (lane & 3) * 2;
                    size_t dst = (size_t)r * CDIM + (gn & 511);
                    __half2 h0; h0.x = __float2half_rn(acc[mi][ni][0]);
                                h0.y = __float2half_rn(acc[mi][ni][1]);
                    __half2 h1; h1.x = __float2half_rn(acc[mi][ni][2]);
                                h1.y = __float2half_rn(acc[mi][ni][3]);
                    *(__half2*)(Cv + dst) = h0;
                    *(__half2*)(Cv + dst + (size_t)8 * CDIM) = h1;
                }
            }
        }
    }
}

// ---------------------------------------------------------------------------
// HMMA attention: block per (n,h), 8 warps x 16 q-rows.
// Q/K arrive pre-RoPE'd (Q pre-scaled) -> staging is pure cp.async for all
// three tiles. QK^T: Q single x K single. P·V: P (normalized) x V single.
// Smem: 3 tiles + mask = ~55KB -> 2 CTAs/SM.
// ---------------------------------------------------------------------------
#define AT_LD 72
#define AT_ROWB 144
#define AT_TILE (128 * AT_ROWB)     // 18432
#define OFF_QHs 0
#define OFF_KHs (1 * AT_TILE)
#define OFF_VHs (2 * AT_TILE)
#define OFF_MKs (3 * AT_TILE)       // 55296
#define ATT2_SMEM (OFF_MKs + 128)   // 55424

__global__ __launch_bounds__(256, 2) void attn2(const __half* __restrict__ Qg,
                                                const __half* __restrict__ Kg,
                                                const __half* __restrict__ Vg,
                                                const unsigned char* __restrict__ pm,
                                                __half* __restrict__ Oh)
{
    extern __shared__ __align__(1024) char smc[];
    const uint32_t sb = smem_to_u32(smc);
    unsigned char* mk = (unsigned char*)(smc + OFF_MKs);

    const int tid  = threadIdx.x;
    const int lane = tid & 31;
    const int wid  = tid >> 5;
    const int n = blockIdx.x, h = blockIdx.y;
    const int b = n >> 6, w = n & 63;

    if (tid < 128) mk[tid] = pm[(size_t)b * TTOT + tid * WDIL + w];

    // Q, K, V tiles: 128 rows x 8 16B-chunks each, pure cp.async
    for (int t = tid; t < 1024; t += 256) {
        int row = t >> 3, ch = t & 7;
        size_t g = ((size_t)(b * TTOT + row * WDIL + w)) * CDIM + h * HDIM + ch * 8;
        uint32_t so = (uint32_t)(row * AT_ROWB + ch * 16);
        CP_ASYNC16(sb + OFF_QHs + so, Qg + g);
        CP_ASYNC16(sb + OFF_KHs + so, Kg + g);
        CP_ASYNC16(sb + OFF_VHs + so, Vg + g);
    }
    CP_COMMIT();
    cp_wait<0>();
    __syncthreads();

    // ===== QK^T: warp tile m16 x n128 x k64 (Q single) =====
    const int qr = wid * 16;
    float c[16][4];
#pragma unroll
    for (int j = 0; j < 16; j++)
#pragma unroll
        for (int v = 0; v < 4; v++) c[j][v] = 0.0f;

#pragma unroll
    for (int kk = 0; kk < 4; kk++) {
        uint32_t ah[4];
        uint32_t abase = sb + OFF_QHs + (uint32_t)((qr + (lane & 15)) * AT_ROWB)
                       + kk * 32 + (lane >> 4) * 16;
        ldsm4(ah, abase);
#pragma unroll
        for (int g = 0; g < 8; g++) {
            uint32_t kaddr = sb + OFF_KHs + (uint32_t)((g * 16 + (lane & 15)) * AT_ROWB)
                           + kk * 32 + (lane >> 4) * 16;
            uint32_t th[4];
            ldsm4(th, kaddr);
            mma2(c[2*g],   ah, th[0], th[2]);
            mma2(c[2*g+1], ah, th[1], th[3]);
        }
    }

    // ===== mask + softmax (normalize P in-place) =====
    float mx0 = -1e30f, mx1 = -1e30f;
#pragma unroll
    for (int j = 0; j < 16; j++) {
        int n0 = j * 8 + (lane & 3) * 2;
        if (mk[n0])     { c[j][0] = -1e30f; c[j][2] = -1e30f; }
        if (mk[n0 + 1]) { c[j][1] = -1e30f; c[j][3] = -1e30f; }
        mx0 = fmaxf(mx0, fmaxf(c[j][0], c[j][1]));
        mx1 = fmaxf(mx1, fmaxf(c[j][2], c[j][3]));
    }
    mx0 = fmaxf(mx0, __shfl_xor_sync(~0u, mx0, 1));
    mx0 = fmaxf(mx0, __shfl_xor_sync(~0u, mx0, 2));
    mx1 = fmaxf(mx1, __shfl_xor_sync(~0u, mx1, 1));
    mx1 = fmaxf(mx1, __shfl_xor_sync(~0u, mx1, 2));
    float s0 = 0.0f, s1 = 0.0f;
#pragma unroll
    for (int j = 0; j < 16; j++) {
        c[j][0] = ex2f(c[j][0] - mx0); s0 += c[j][0];
        c[j][1] = ex2f(c[j][1] - mx0); s0 += c[j][1];
        c[j][2] = ex2f(c[j][2] - mx1); s1 += c[j][2];
        c[j][3] = ex2f(c[j][3] - mx1); s1 += c[j][3];
    }
    s0 += __shfl_xor_sync(~0u, s0, 1); s0 += __shfl_xor_sync(~0u, s0, 2);
    s1 += __shfl_xor_sync(~0u, s1, 1); s1 += __shfl_xor_sync(~0u, s1, 2);
    const float inv0 = 1.0f / s0, inv1 = 1.0f / s1;
#pragma unroll
    for (int j = 0; j < 16; j++) {
        c[j][0] *= inv0; c[j][1] *= inv0;
        c[j][2] *= inv1; c[j][3] *= inv1;
    }

    // ===== P @ V: m16 x n64 x k128 (P normalized fp16, V single) =====
    float o[8][4];
#pragma unroll
    for (int j = 0; j < 8; j++)
#pragma unroll
        for (int v = 0; v < 4; v++) o[j][v] = 0.0f;

#pragma unroll
    for (int t = 0; t < 8; t++) {
        uint32_t pa[4];
#pragma unroll
        for (int q = 0; q < 4; q++) {
            int jt = 2 * t + (q >> 1);
            pa[q] = packh(c[jt][(q & 1) * 2], c[jt][(q & 1) * 2 + 1]);
        }
#pragma unroll
        for (int gg = 0; gg < 4; gg++) {
            uint32_t vaddr = sb + OFF_VHs
                + (uint32_t)((t * 16 + (lane & 7) + ((lane >> 3) & 1) * 8) * AT_ROWB)
                + gg * 32 + (lane >> 4) * 16;
            uint32_t vh[4];
            ldsm4t(vh, vaddr);
            mma2(o[2*gg],   pa, vh[0], vh[1]);
            mma2(o[2*gg+1], pa, vh[2], vh[3]);
        }
    }

    // ===== epilogue: single fp16 store =====
    const int r0 = qr + (lane >> 2);
#pragma unroll
    for (int j2 = 0; j2 < 8; j2++) {
        int d0 = j2 * 8 + (lane & 3) * 2;
        size_t g0 = ((size_t)(b * TTOT + r0 * WDIL + w)) * CDIM + h * HDIM + d0;
        size_t g1 = g0 + (size_t)8 * WDIL * CDIM;
        __half2 hv;
        hv.x = __float2half_rn(o[j2][0]);
        hv.y = __float2half_rn(o[j2][1]);
        *(__half2*)(Oh + g0) = hv;
        hv.x = __float2half_rn(o[j2][2]);
        hv.y = __float2half_rn(o[j2][3]);
        *(__half2*)(Oh + g1) = hv;
    }
}

// ---------------------------------------------------------------------------
// Launch (serial, NULL stream)
// ---------------------------------------------------------------------------
extern "C" void kernel_launch(void* const* d_in, const int* in_sizes, int n_in,
                              void* d_out, int out_size)
{
    const float*         x  = (const float*)d_in[0];
    const unsigned char* pm = (const unsigned char*)d_in[1];
    const float*         Wq = (const float*)d_in[2];
    const float*         Wk = (const float*)d_in[3];
    const float*         Wv = (const float*)d_in[4];
    const float*         Wo = (const float*)d_in[5];
    float*               out = (float*)d_out;

    __half *xh, *qh, *kh, *vh, *oh, *bq, *bo;
    float *ctab, *stab;
    cudaGetSymbolAddress((void**)&xh, g_xh);
    cudaGetSymbolAddress((void**)&qh, g_Qh);
    cudaGetSymbolAddress((void**)&kh, g_Kh);
    cudaGetSymbolAddress((void**)&vh, g_Vh);
    cudaGetSymbolAddress((void**)&oh, g_Oh);
    cudaGetSymbolAddress((void**)&bq, g_Bq);
    cudaGetSymbolAddress((void**)&bo, g_Bo);
    cudaGetSymbolAddress((void**)&ctab, g_cos);
    cudaGetSymbolAddress((void**)&stab, g_sin);

    cudaFuncSetAttribute((const void*)tc_gemm<1>,
                         cudaFuncAttributeMaxDynamicSharedMemorySize, GEMM_SMEM);
    cudaFuncSetAttribute((const void*)tc_gemm<0>,
                         cudaFuncAttributeMaxDynamicSharedMemorySize, GEMM_SMEM);
    cudaFuncSetAttribute(attn2, cudaFuncAttributeMaxDynamicSharedMemorySize, ATT2_SMEM);

    // 1) fused conversions + RoPE tables (one launch)
    prep<<<NB_PREP, 256>>>(x, Wq, Wk, Wv, Wo, xh, bq, bo, ctab, stab);

    // 2) fused QKV projection -> Q (RoPE+scale) | K (RoPE) | V, all fp16
    tc_gemm<1><<<dim3(6, MROWS / 128), 256, GEMM_SMEM>>>(xh, bq,
                                                         nullptr, qh, kh, vh,
                                                         ctab, stab);

    // 3) HMMA attention -> O fp16
    attn2<<<dim3(256, NHEAD), 256, ATT2_SMEM>>>(qh, kh, vh, pm, oh);

    // 4) output projection (single-term A = Oh) -> d_out (f32)
    tc_gemm<0><<<dim3(2, MROWS / 128), 256, GEMM_SMEM>>>(oh, bo,
                                                         out, nullptr, nullptr, nullptr,
                                                         nullptr, nullptr);
}